// round 12
// baseline (speedup 1.0000x reference)
#include <cuda_runtime.h>

// Problem constants (fixed shapes per reference)
#define BQ 16
#define NN 16384
#define DD 128
#define EE 65536
#define MM (BQ * NN)   // 262144 rows

// ---------------- scratch (__device__ globals; no cudaMalloc allowed) ----------------
__device__ int   g_edge64;           // 1 if edge_index buffer is int64, 0 if int32
__device__ int   g_deg[NN];
__device__ int   g_rowstart[NN + 1];
__device__ int   g_cursor[NN];
__device__ int   g_nbr[EE];
// yz[row][0:128] = x@W_self.T,  yz[row][128:256] = x@W_neigh.T
__device__ float g_yz[(size_t)MM * 256];

// ---------------- edge dtype detection ----------------
// int64 edges with values in [0,16384) => every odd int32 word is 0 (high half).
// int32 edges => odd words are random node ids; P(128 all zero) = 16384^-128 ~ 0.
__global__ void k_detect(const int* __restrict__ e32) {
    if (threadIdx.x == 0) {
        int any = 0;
        for (int i = 1; i < 256; i += 2) any |= e32[i];
        g_edge64 = (any == 0) ? 1 : 0;
    }
}

__device__ __forceinline__ int edge_at(const void* edge, int idx) {
    int v;
    if (g_edge64) v = (int)((const long long*)edge)[idx];
    else          v = ((const int*)edge)[idx];
    return v & (NN - 1);   // no-op for valid data; prevents any OOB crash
}

// ---------------- CSR build ----------------
__global__ void k_zero_deg() {
    int i = blockIdx.x * blockDim.x + threadIdx.x;
    if (i < NN) g_deg[i] = 0;
}

__global__ void k_count(const void* __restrict__ edge) {
    int e = blockIdx.x * blockDim.x + threadIdx.x;
    if (e < EE) {
        int dst = edge_at(edge, EE + e);
        atomicAdd(&g_deg[dst], 1);
    }
}

// 1 block, 512 threads; each owns a chunk of 32 entries.
__global__ void k_scan() {
    __shared__ int part[512];
    int t = threadIdx.x;
    int base_i = t * 32;
    int local[32];
    int s = 0;
#pragma unroll
    for (int i = 0; i < 32; ++i) { local[i] = s; s += g_deg[base_i + i]; }
    part[t] = s;
    __syncthreads();
    if (t == 0) {
        int acc = 0;
        for (int u = 0; u < 512; ++u) { int v = part[u]; part[u] = acc; acc += v; }
        g_rowstart[NN] = acc;   // == EE
    }
    __syncthreads();
    int b = part[t];
#pragma unroll
    for (int i = 0; i < 32; ++i) {
        int rs = b + local[i];
        g_rowstart[base_i + i] = rs;
        g_cursor[base_i + i]   = rs;
    }
}

__global__ void k_fill(const void* __restrict__ edge) {
    int e = blockIdx.x * blockDim.x + threadIdx.x;
    if (e < EE) {
        int src = edge_at(edge, e);
        int dst = edge_at(edge, EE + e);
        int p = atomicAdd(&g_cursor[dst], 1);
        g_nbr[p] = src;
    }
}

// ---------------- GEMM: C[M,256] = x[M,128] @ [W_self; W_neigh]^T ----------------
// CTA: 256 threads, BM=64 rows, BN=256 cols (both W halves), K=128 fully resident.
// Thread micro-tile: 8 rows x (4 y-cols + 4 z-cols).
// Shared: As[64][128] natural (32KB) + Bs[k][n] transposed (128KB) = 160KB dynamic.
#define GEMM_SMEM_FLOATS (64 * 128 + 128 * 256)
#define GEMM_SMEM_BYTES  (GEMM_SMEM_FLOATS * 4)

__global__ void __launch_bounds__(256, 1)
k_gemm(const float* __restrict__ x,
       const float* __restrict__ Ws,
       const float* __restrict__ Wn) {
    extern __shared__ float sm[];
    float* As = sm;                 // [m][k]  m<64, k<128
    float* Bs = sm + 64 * 128;      // [k][n]  k<128, n<256

    const int tid = threadIdx.x;
    const int tn  = tid & 31;       // col group: cols tn*4 (+128 for z half)
    const int tm  = tid >> 5;       // row group: rows tm*8..tm*8+7

    // Load + transpose Wcat into Bs[k][n]. 8192 float4s / 256 threads = 32 iters.
    // Lanes write consecutive n at fixed k -> conflict-free STS.
#pragma unroll 4
    for (int it = 0; it < 32; ++it) {
        int idx = tid + 256 * it;
        int n  = idx & 255;
        int k4 = idx >> 8;          // 0..31
        const float* srcp = (n < 128) ? (Ws + n * 128 + k4 * 4)
                                      : (Wn + (n - 128) * 128 + k4 * 4);
        float4 v = *(const float4*)srcp;
        Bs[(4 * k4 + 0) * 256 + n] = v.x;
        Bs[(4 * k4 + 1) * 256 + n] = v.y;
        Bs[(4 * k4 + 2) * 256 + n] = v.z;
        Bs[(4 * k4 + 3) * 256 + n] = v.w;
    }

    for (int m0 = blockIdx.x * 64; m0 < MM; m0 += gridDim.x * 64) {
        __syncthreads();  // previous-iter readers done (also fences Bs on iter 0)
        // Coalesced copy of 64 x-rows into As (natural layout, float4 both sides).
#pragma unroll
        for (int it = 0; it < 8; ++it) {
            int idx = tid + 256 * it;
            int k4 = idx & 31;
            int m  = idx >> 5;
            *(float4*)&As[m * 128 + k4 * 4] =
                *(const float4*)&x[(size_t)(m0 + m) * 128 + k4 * 4];
        }
        __syncthreads();

        float acc[8][8];
#pragma unroll
        for (int r = 0; r < 8; ++r)
#pragma unroll
            for (int c = 0; c < 8; ++c) acc[r][c] = 0.f;

#pragma unroll 8
        for (int k = 0; k < 128; ++k) {
            float4 by = *(float4*)&Bs[k * 256 + tn * 4];
            float4 bz = *(float4*)&Bs[k * 256 + 128 + tn * 4];
#pragma unroll
            for (int r = 0; r < 8; ++r) {
                float a = As[(tm * 8 + r) * 128 + k];
                acc[r][0] += a * by.x; acc[r][1] += a * by.y;
                acc[r][2] += a * by.z; acc[r][3] += a * by.w;
                acc[r][4] += a * bz.x; acc[r][5] += a * bz.y;
                acc[r][6] += a * bz.z; acc[r][7] += a * bz.w;
            }
        }

#pragma unroll
        for (int r = 0; r < 8; ++r) {
            size_t row = (size_t)m0 + tm * 8 + r;
            *(float4*)&g_yz[row * 256 + tn * 4] =
                make_float4(acc[r][0], acc[r][1], acc[r][2], acc[r][3]);
            *(float4*)&g_yz[row * 256 + 128 + tn * 4] =
                make_float4(acc[r][4], acc[r][5], acc[r][6], acc[r][7]);
        }
    }
}

// ---------------- gather + bias + LayerNorm + ReLU ----------------
// One CTA (128 threads) per output row; thread j owns column j.
__global__ void k_final(const float* __restrict__ bias,
                        const float* __restrict__ gamma,
                        const float* __restrict__ beta,
                        float* __restrict__ out) {
    const int row = blockIdx.x;
    const int i   = row & (NN - 1);   // graph-local node id
    const int b   = row >> 14;        // batch id (N = 2^14)
    const int j   = threadIdx.x;

    float v = g_yz[(size_t)row * 256 + j];          // self term (y half)

    int st = g_rowstart[i];
    int en = g_rowstart[i + 1];
    float s = 0.f;
    for (int p = st; p < en; ++p) {
        int src = g_nbr[p] & (NN - 1);
        s += g_yz[((size_t)(b * NN + src)) * 256 + 128 + j];   // z half
    }
    float dg = (float)(en - st);
    v += s / fmaxf(dg, 1.f) + bias[j];

    // LayerNorm over 128 cols (two-pass: mean, then centered variance)
    __shared__ float red[4];
    const int lane = j & 31, wid = j >> 5;

    float t = v;
    t += __shfl_xor_sync(0xffffffff, t, 16);
    t += __shfl_xor_sync(0xffffffff, t, 8);
    t += __shfl_xor_sync(0xffffffff, t, 4);
    t += __shfl_xor_sync(0xffffffff, t, 2);
    t += __shfl_xor_sync(0xffffffff, t, 1);
    if (lane == 0) red[wid] = t;
    __syncthreads();
    float mu = (red[0] + red[1] + red[2] + red[3]) * (1.f / 128.f);
    __syncthreads();  // all reads of red done before reuse

    float c = v - mu;
    t = c * c;
    t += __shfl_xor_sync(0xffffffff, t, 16);
    t += __shfl_xor_sync(0xffffffff, t, 8);
    t += __shfl_xor_sync(0xffffffff, t, 4);
    t += __shfl_xor_sync(0xffffffff, t, 2);
    t += __shfl_xor_sync(0xffffffff, t, 1);
    if (lane == 0) red[wid] = t;
    __syncthreads();
    float var = (red[0] + red[1] + red[2] + red[3]) * (1.f / 128.f);

    float o = c * rsqrtf(var + 1e-5f) * gamma[j] + beta[j];
    out[(size_t)row * 128 + j] = fmaxf(o, 0.f);
}

// ---------------- launch ----------------
extern "C" void kernel_launch(void* const* d_in, const int* in_sizes, int n_in,
                              void* d_out, int out_size) {
    const float* x    = (const float*)d_in[0];
    const void*  edge = d_in[1];           // int32 or int64 — detected on device
    // batch_size may or may not appear as a buffer; anchor trailing params to the end.
    int base = n_in - 5;
    const float* Ws    = (const float*)d_in[base + 0];
    const float* Wn    = (const float*)d_in[base + 1];
    const float* bias  = (const float*)d_in[base + 2];
    const float* gamma = (const float*)d_in[base + 3];
    const float* beta  = (const float*)d_in[base + 4];

    cudaFuncSetAttribute(k_gemm, cudaFuncAttributeMaxDynamicSharedMemorySize,
                         GEMM_SMEM_BYTES);

    k_detect<<<1, 32>>>((const int*)edge);
    k_zero_deg<<<(NN + 255) / 256, 256>>>();
    k_count<<<(EE + 255) / 256, 256>>>(edge);
    k_scan<<<1, 512>>>();
    k_fill<<<(EE + 255) / 256, 256>>>(edge);
    k_gemm<<<152, 256, GEMM_SMEM_BYTES>>>(x, Ws, Wn);
    k_final<<<MM, 128>>>(bias, gamma, beta, (float*)d_out);
}

// round 15
// speedup vs baseline: 1.4486x; 1.4486x over previous
#include <cuda_runtime.h>
#include <cuda_bf16.h>
#include <cstdint>

// Problem constants (fixed shapes per reference)
#define BQ 16
#define NN 16384
#define DD 128
#define EE 65536
#define MM (BQ * NN)        // 262144 rows
#define NTILES (MM / 128)   // 2048

// ---------------- scratch (__device__ globals; no cudaMalloc allowed) ----------------
__device__ int   g_edge64;           // 1 if edge_index buffer is int64, 0 if int32
__device__ int   g_deg[NN];
__device__ int   g_rowstart[NN + 1];
__device__ int   g_cursor[NN];
__device__ int   g_nbr[EE];
// yz[row][0:128] = x@W_self.T,  yz[row][128:256] = x@W_neigh.T
__device__ float g_yz[(size_t)MM * 256];

// ---------------- small helpers ----------------
__device__ __forceinline__ uint32_t smem_u32(const void* p) {
    uint32_t a;
    asm("{ .reg .u64 t; cvta.to.shared.u64 t, %1; cvt.u32.u64 %0, t; }" : "=r"(a) : "l"(p));
    return a;
}
__device__ __forceinline__ uint32_t bf16x2_of(float lo, float hi) {
    __nv_bfloat162 t = __floats2bfloat162_rn(lo, hi);
    return *(uint32_t*)&t;
}
__device__ __forceinline__ void ldsm4(uint32_t& r0, uint32_t& r1, uint32_t& r2, uint32_t& r3,
                                      uint32_t addr) {
    asm volatile("ldmatrix.sync.aligned.m8n8.x4.shared.b16 {%0,%1,%2,%3}, [%4];"
                 : "=r"(r0), "=r"(r1), "=r"(r2), "=r"(r3) : "r"(addr));
}
__device__ __forceinline__ void mma16816(float* c,
                                         uint32_t a0, uint32_t a1, uint32_t a2, uint32_t a3,
                                         uint32_t b0, uint32_t b1) {
    asm volatile("mma.sync.aligned.m16n8k16.row.col.f32.bf16.bf16.f32 "
                 "{%0,%1,%2,%3}, {%4,%5,%6,%7}, {%8,%9}, {%0,%1,%2,%3};"
                 : "+f"(c[0]), "+f"(c[1]), "+f"(c[2]), "+f"(c[3])
                 : "r"(a0), "r"(a1), "r"(a2), "r"(a3), "r"(b0), "r"(b1));
}

// ---------------- edge dtype detection + deg zero (fused) ----------------
__global__ void k_init(const int* __restrict__ e32) {
    int i = blockIdx.x * blockDim.x + threadIdx.x;
    if (i < NN) g_deg[i] = 0;
    if (i == 0) {
        int any = 0;
        for (int k = 1; k < 256; k += 2) any |= e32[k];
        g_edge64 = (any == 0) ? 1 : 0;
    }
}

__device__ __forceinline__ int edge_at(const void* edge, int idx) {
    int v;
    if (g_edge64) v = (int)((const long long*)edge)[idx];
    else          v = ((const int*)edge)[idx];
    return v & (NN - 1);
}

__global__ void k_count(const void* __restrict__ edge) {
    int e = blockIdx.x * blockDim.x + threadIdx.x;
    if (e < EE) atomicAdd(&g_deg[edge_at(edge, EE + e)], 1);
}

// two-level shfl scan; 512 threads x 32 entries
__global__ void k_scan() {
    __shared__ int wsum[16];
    int t = threadIdx.x;
    int base = t * 32;
    int local[32];
    int s = 0;
#pragma unroll
    for (int i = 0; i < 32; ++i) { local[i] = s; s += g_deg[base + i]; }
    int lane = t & 31, w = t >> 5;
    int v = s;
#pragma unroll
    for (int d = 1; d < 32; d <<= 1) {
        int u = __shfl_up_sync(0xffffffffu, v, d);
        if (lane >= d) v += u;
    }
    if (lane == 31) wsum[w] = v;
    __syncthreads();
    if (t < 16) {
        int x = wsum[t];
#pragma unroll
        for (int d = 1; d < 16; d <<= 1) {
            int u = __shfl_up_sync(0x0000ffffu, x, d);
            if (t >= d) x += u;
        }
        wsum[t] = x;
    }
    __syncthreads();
    int excl = v - s + (w ? wsum[w - 1] : 0);
    if (t == 511) g_rowstart[NN] = wsum[15];
#pragma unroll
    for (int i = 0; i < 32; ++i) {
        int rs = excl + local[i];
        g_rowstart[base + i] = rs;
        g_cursor[base + i]   = rs;
    }
}

__global__ void k_fill(const void* __restrict__ edge) {
    int e = blockIdx.x * blockDim.x + threadIdx.x;
    if (e < EE) {
        int src = edge_at(edge, e);
        int dst = edge_at(edge, EE + e);
        int p = atomicAdd(&g_cursor[dst], 1);
        g_nbr[p] = src;
    }
}

// ==========================================================================
// HMMA GEMM: C[M,256] = x[M,128] @ [W_self; W_neigh]^T  (3-term bf16 split)
// Per CTA: BM=128, BN=256, K=128 fully resident. 8 warps = 2(M) x 4(N),
// warp tile 64x64, mma.m16n8k16 fragments via ldmatrix.x4.
// SMEM rows padded to 136 bf16 (272B) -> conflict-free STS and LDSM.
// ==========================================================================
#define RSTR   136                       // bf16 units per padded row
#define RSTRB  (RSTR * 2)                // 272 bytes
#define SM_AH  0
#define SM_AL  (SM_AH + 128 * RSTRB)     // 34816
#define SM_BH  (SM_AL + 128 * RSTRB)     // 69632
#define SM_BL  (SM_BH + 256 * RSTRB)     // 139264
#define SM_TOT (SM_BL + 256 * RSTRB)     // 208896 bytes

__global__ void __launch_bounds__(256, 1)
k_gemm_mma(const float* __restrict__ x,
           const float* __restrict__ Ws,
           const float* __restrict__ Wn) {
    extern __shared__ char sm[];
    const uint32_t smb = smem_u32(sm);
    const int tid    = threadIdx.x;
    const int lane   = tid & 31;
    const int wid    = tid >> 5;
    const int warp_m = wid & 1;    // 0..1  -> m offset 0/64
    const int warp_n = wid >> 1;   // 0..3  -> n offset 0/64/128/192

    // ---- stage + split W once: 8192 float4 / 256 thr = 32 iters ----
#pragma unroll 4
    for (int it = 0; it < 32; ++it) {
        int idx = tid + 256 * it;
        int row = idx >> 5;            // 0..255 (output col n)
        int col = (idx & 31) * 4;      // k
        const float* sp = (row < 128) ? (Ws + row * 128 + col)
                                      : (Wn + (row - 128) * 128 + col);
        float4 v = *(const float4*)sp;
        float h0 = __bfloat162float(__float2bfloat16(v.x));
        float h1 = __bfloat162float(__float2bfloat16(v.y));
        float h2 = __bfloat162float(__float2bfloat16(v.z));
        float h3 = __bfloat162float(__float2bfloat16(v.w));
        uint32_t off = row * RSTRB + col * 2;
        *(uint2*)(sm + SM_BH + off) = make_uint2(bf16x2_of(h0, h1), bf16x2_of(h2, h3));
        *(uint2*)(sm + SM_BL + off) = make_uint2(bf16x2_of(v.x - h0, v.y - h1),
                                                 bf16x2_of(v.z - h2, v.w - h3));
    }

    // ldmatrix per-thread base offsets (row part), computed once
    const uint32_t a_row = (uint32_t)(warp_m * 64 + (lane & 15));             // + mf*16
    const uint32_t a_kb  = (uint32_t)((lane >> 4) * 16);                      // + ks*32
    const uint32_t b_row = (uint32_t)(warp_n * 64 + (lane & 7) + ((lane >> 4) << 3)); // + nfp*16
    const uint32_t b_kb  = (uint32_t)(((lane >> 3) & 1) * 16);                // + ks*32

    for (int t = blockIdx.x; t < NTILES; t += gridDim.x) {
        const size_t m0 = (size_t)t * 128;
        __syncthreads();   // all warps done reading previous A tile

        // ---- stage + split A tile: 4096 float4 / 256 thr = 16 iters ----
#pragma unroll
        for (int it = 0; it < 16; ++it) {
            int idx = tid + 256 * it;
            int row = idx >> 5;
            int col = (idx & 31) * 4;
            float4 v = *(const float4*)&x[(m0 + row) * 128 + col];
            float h0 = __bfloat162float(__float2bfloat16(v.x));
            float h1 = __bfloat162float(__float2bfloat16(v.y));
            float h2 = __bfloat162float(__float2bfloat16(v.z));
            float h3 = __bfloat162float(__float2bfloat16(v.w));
            uint32_t off = row * RSTRB + col * 2;
            *(uint2*)(sm + SM_AH + off) = make_uint2(bf16x2_of(h0, h1), bf16x2_of(h2, h3));
            *(uint2*)(sm + SM_AL + off) = make_uint2(bf16x2_of(v.x - h0, v.y - h1),
                                                     bf16x2_of(v.z - h2, v.w - h3));
        }
        __syncthreads();

        float c[4][8][4];
#pragma unroll
        for (int mf = 0; mf < 4; ++mf)
#pragma unroll
            for (int nf = 0; nf < 8; ++nf)
#pragma unroll
                for (int q = 0; q < 4; ++q) c[mf][nf][q] = 0.f;

#pragma unroll 1
        for (int split = 0; split < 3; ++split) {
            const uint32_t abase = smb + ((split == 2) ? SM_AL : SM_AH);
            const uint32_t bbase = smb + ((split == 1) ? SM_BL : SM_BH);
#pragma unroll 1
            for (int ks = 0; ks < 8; ++ks) {
                const uint32_t kso = (uint32_t)ks * 32;
                uint32_t b[8][2];
#pragma unroll
                for (int nfp = 0; nfp < 4; ++nfp) {
                    uint32_t r0, r1, r2, r3;
                    ldsm4(r0, r1, r2, r3,
                          bbase + (b_row + nfp * 16) * RSTRB + kso + b_kb);
                    b[2 * nfp][0] = r0; b[2 * nfp][1] = r1;
                    b[2 * nfp + 1][0] = r2; b[2 * nfp + 1][1] = r3;
                }
#pragma unroll
                for (int mf = 0; mf < 4; ++mf) {
                    uint32_t a0, a1, a2, a3;
                    ldsm4(a0, a1, a2, a3,
                          abase + (a_row + mf * 16) * RSTRB + kso + a_kb);
#pragma unroll
                    for (int nf = 0; nf < 8; ++nf)
                        mma16816(c[mf][nf], a0, a1, a2, a3, b[nf][0], b[nf][1]);
                }
            }
        }

        // ---- epilogue: scatter fragments to g_yz ----
#pragma unroll
        for (int mf = 0; mf < 4; ++mf) {
            size_t row = m0 + warp_m * 64 + mf * 16 + (lane >> 2);
#pragma unroll
            for (int nf = 0; nf < 8; ++nf) {
                int col = warp_n * 64 + nf * 8 + (lane & 3) * 2;
                *(float2*)&g_yz[row * 256 + col]       = make_float2(c[mf][nf][0], c[mf][nf][1]);
                *(float2*)&g_yz[(row + 8) * 256 + col] = make_float2(c[mf][nf][2], c[mf][nf][3]);
            }
        }
    }
}

// ---------------- gather + bias + LayerNorm + ReLU ----------------
__global__ void k_final(const float* __restrict__ bias,
                        const float* __restrict__ gamma,
                        const float* __restrict__ beta,
                        float* __restrict__ out) {
    const int row = blockIdx.x;
    const int i   = row & (NN - 1);
    const int b   = row >> 14;
    const int j   = threadIdx.x;

    float v = g_yz[(size_t)row * 256 + j];

    int st = g_rowstart[i];
    int en = g_rowstart[i + 1];
    float s = 0.f;
    for (int p = st; p < en; ++p) {
        int src = g_nbr[p] & (NN - 1);
        s += g_yz[((size_t)(b * NN + src)) * 256 + 128 + j];
    }
    float dg = (float)(en - st);
    v += s / fmaxf(dg, 1.f) + bias[j];

    __shared__ float red[4];
    const int lane = j & 31, wid = j >> 5;

    float t = v;
    t += __shfl_xor_sync(0xffffffff, t, 16);
    t += __shfl_xor_sync(0xffffffff, t, 8);
    t += __shfl_xor_sync(0xffffffff, t, 4);
    t += __shfl_xor_sync(0xffffffff, t, 2);
    t += __shfl_xor_sync(0xffffffff, t, 1);
    if (lane == 0) red[wid] = t;
    __syncthreads();
    float mu = (red[0] + red[1] + red[2] + red[3]) * (1.f / 128.f);
    __syncthreads();

    float c = v - mu;
    t = c * c;
    t += __shfl_xor_sync(0xffffffff, t, 16);
    t += __shfl_xor_sync(0xffffffff, t, 8);
    t += __shfl_xor_sync(0xffffffff, t, 4);
    t += __shfl_xor_sync(0xffffffff, t, 2);
    t += __shfl_xor_sync(0xffffffff, t, 1);
    if (lane == 0) red[wid] = t;
    __syncthreads();
    float var = (red[0] + red[1] + red[2] + red[3]) * (1.f / 128.f);

    float o = c * rsqrtf(var + 1e-5f) * gamma[j] + beta[j];
    out[(size_t)row * 128 + j] = fmaxf(o, 0.f);
}

// ---------------- launch ----------------
extern "C" void kernel_launch(void* const* d_in, const int* in_sizes, int n_in,
                              void* d_out, int out_size) {
    const float* x    = (const float*)d_in[0];
    const void*  edge = d_in[1];
    int base = n_in - 5;
    const float* Ws    = (const float*)d_in[base + 0];
    const float* Wn    = (const float*)d_in[base + 1];
    const float* bias  = (const float*)d_in[base + 2];
    const float* gamma = (const float*)d_in[base + 3];
    const float* beta  = (const float*)d_in[base + 4];

    cudaFuncSetAttribute(k_gemm_mma, cudaFuncAttributeMaxDynamicSharedMemorySize, SM_TOT);

    k_init<<<(NN + 255) / 256, 256>>>((const int*)edge);
    k_count<<<(EE + 255) / 256, 256>>>(edge);
    k_scan<<<1, 512>>>();
    k_fill<<<(EE + 255) / 256, 256>>>(edge);
    k_gemm_mma<<<152, 256, SM_TOT>>>(x, Ws, Wn);
    k_final<<<MM, 128>>>(bias, gamma, beta, (float*)d_out);
}

// round 17
// speedup vs baseline: 1.5375x; 1.0614x over previous
#include <cuda_runtime.h>
#include <cuda_bf16.h>
#include <cstdint>

// Problem constants (fixed shapes per reference)
#define BQ 16
#define NN 16384
#define DD 128
#define EE 65536
#define MM (BQ * NN)        // 262144 rows
#define NT2 (MM / 64)       // 4096 tiles of 64 rows

// ---------------- scratch (__device__ globals; no cudaMalloc allowed) ----------------
__device__ int   g_edge64;           // 1 if edge_index buffer is int64, 0 if int32
__device__ int   g_deg[NN];
__device__ int   g_rowstart[NN + 1];
__device__ int   g_cursor[NN];
__device__ int   g_nbr[EE];
// yz[row][0:128] = x@W_self.T,  yz[row][128:256] = x@W_neigh.T
__device__ float g_yz[(size_t)MM * 256];

// ---------------- small helpers ----------------
__device__ __forceinline__ uint32_t smem_u32(const void* p) {
    uint32_t a;
    asm("{ .reg .u64 t; cvta.to.shared.u64 t, %1; cvt.u32.u64 %0, t; }" : "=r"(a) : "l"(p));
    return a;
}
__device__ __forceinline__ uint32_t bf16x2_of(float lo, float hi) {
    __nv_bfloat162 t = __floats2bfloat162_rn(lo, hi);
    return *(uint32_t*)&t;
}
__device__ __forceinline__ void ldsm4(uint32_t& r0, uint32_t& r1, uint32_t& r2, uint32_t& r3,
                                      uint32_t addr) {
    asm volatile("ldmatrix.sync.aligned.m8n8.x4.shared.b16 {%0,%1,%2,%3}, [%4];"
                 : "=r"(r0), "=r"(r1), "=r"(r2), "=r"(r3) : "r"(addr));
}
__device__ __forceinline__ void mma16816(float* c,
                                         uint32_t a0, uint32_t a1, uint32_t a2, uint32_t a3,
                                         uint32_t b0, uint32_t b1) {
    asm volatile("mma.sync.aligned.m16n8k16.row.col.f32.bf16.bf16.f32 "
                 "{%0,%1,%2,%3}, {%4,%5,%6,%7}, {%8,%9}, {%0,%1,%2,%3};"
                 : "+f"(c[0]), "+f"(c[1]), "+f"(c[2]), "+f"(c[3])
                 : "r"(a0), "r"(a1), "r"(a2), "r"(a3), "r"(b0), "r"(b1));
}

// ---------------- edge dtype detection + deg zero (fused) ----------------
__global__ void k_init(const int* __restrict__ e32) {
    int i = blockIdx.x * blockDim.x + threadIdx.x;
    if (i < NN) g_deg[i] = 0;
    if (i == 0) {
        int any = 0;
        for (int k = 1; k < 256; k += 2) any |= e32[k];
        g_edge64 = (any == 0) ? 1 : 0;
    }
}

__device__ __forceinline__ int edge_at(const void* edge, int idx) {
    int v;
    if (g_edge64) v = (int)((const long long*)edge)[idx];
    else          v = ((const int*)edge)[idx];
    return v & (NN - 1);
}

__global__ void k_count(const void* __restrict__ edge) {
    int e = blockIdx.x * blockDim.x + threadIdx.x;
    if (e < EE) atomicAdd(&g_deg[edge_at(edge, EE + e)], 1);
}

// two-level shfl scan; 512 threads x 32 entries
__global__ void k_scan() {
    __shared__ int wsum[16];
    int t = threadIdx.x;
    int base = t * 32;
    int local[32];
    int s = 0;
#pragma unroll
    for (int i = 0; i < 32; ++i) { local[i] = s; s += g_deg[base + i]; }
    int lane = t & 31, w = t >> 5;
    int v = s;
#pragma unroll
    for (int d = 1; d < 32; d <<= 1) {
        int u = __shfl_up_sync(0xffffffffu, v, d);
        if (lane >= d) v += u;
    }
    if (lane == 31) wsum[w] = v;
    __syncthreads();
    if (t < 16) {
        int x = wsum[t];
#pragma unroll
        for (int d = 1; d < 16; d <<= 1) {
            int u = __shfl_up_sync(0x0000ffffu, x, d);
            if (t >= d) x += u;
        }
        wsum[t] = x;
    }
    __syncthreads();
    int excl = v - s + (w ? wsum[w - 1] : 0);
    if (t == 511) g_rowstart[NN] = wsum[15];
#pragma unroll
    for (int i = 0; i < 32; ++i) {
        int rs = excl + local[i];
        g_rowstart[base + i] = rs;
        g_cursor[base + i]   = rs;
    }
}

__global__ void k_fill(const void* __restrict__ edge) {
    int e = blockIdx.x * blockDim.x + threadIdx.x;
    if (e < EE) {
        int src = edge_at(edge, e);
        int dst = edge_at(edge, EE + e);
        int p = atomicAdd(&g_cursor[dst], 1);
        g_nbr[p] = src;
    }
}

// ==========================================================================
// HMMA GEMM v2: C[M,256] = x[M,128] @ [W_self; W_neigh]^T, 3-term bf16 split,
// BM=64, BN=256, K=128. 8 warps = 2(M) x 4(N), warp tile 32x64.
// Double-buffered A (2 bufs x hi/lo) + register prefetch of next tile:
// per iter: STS(t) -> sync -> issue LDG(t+1) -> MMA(t) -> epilogue(t).
// SMEM rows padded to 136 bf16 (272B) -> conflict-free STS and LDSM.
// ==========================================================================
#define RSTR   136                       // bf16 units per padded row
#define RSTRB  (RSTR * 2)                // 272 bytes
#define SM_BH  0
#define SM_BL  (SM_BH + 256 * RSTRB)     // 69632
#define SM_A0  (SM_BL + 256 * RSTRB)     // 139264; A: buf*34816 + split*17408
#define SM_TOT (SM_A0 + 4 * 64 * RSTRB)  // 208896 bytes

__global__ void __launch_bounds__(256, 1)
k_gemm_mma(const float* __restrict__ x,
           const float* __restrict__ Ws,
           const float* __restrict__ Wn) {
    extern __shared__ char sm[];
    const uint32_t smb = smem_u32(sm);
    const int tid    = threadIdx.x;
    const int lane   = tid & 31;
    const int wid    = tid >> 5;
    const int warp_m = wid & 1;    // 0..1  -> m offset 0/32
    const int warp_n = wid >> 1;   // 0..3  -> n offset 0/64/128/192

    // ---- stage + split W once: 8192 float4 / 256 thr = 32 iters ----
#pragma unroll 4
    for (int it = 0; it < 32; ++it) {
        int idx = tid + 256 * it;
        int row = idx >> 5;            // 0..255 (output col n)
        int col = (idx & 31) * 4;      // k
        const float* sp = (row < 128) ? (Ws + row * 128 + col)
                                      : (Wn + (row - 128) * 128 + col);
        float4 v = *(const float4*)sp;
        float h0 = __bfloat162float(__float2bfloat16(v.x));
        float h1 = __bfloat162float(__float2bfloat16(v.y));
        float h2 = __bfloat162float(__float2bfloat16(v.z));
        float h3 = __bfloat162float(__float2bfloat16(v.w));
        uint32_t off = row * RSTRB + col * 2;
        *(uint2*)(sm + SM_BH + off) = make_uint2(bf16x2_of(h0, h1), bf16x2_of(h2, h3));
        *(uint2*)(sm + SM_BL + off) = make_uint2(bf16x2_of(v.x - h0, v.y - h1),
                                                 bf16x2_of(v.z - h2, v.w - h3));
    }
    // (first in-loop __syncthreads covers B visibility)

    // per-thread staging coords: 8 float4 per tile (row=idx>>5 in 0..63)
    const int st_row = tid >> 5;           // + 8*it
    const int st_col = (tid & 31) * 4;

    // ldmatrix per-thread base offsets
    const uint32_t a_row = (uint32_t)(warp_m * 32 + (lane & 15));             // + mf*16
    const uint32_t a_kb  = (uint32_t)((lane >> 4) * 16);                      // + ks*32
    const uint32_t b_row = (uint32_t)(warp_n * 64 + (lane & 7) + ((lane >> 4) << 3)); // + nfp*16
    const uint32_t b_kb  = (uint32_t)(((lane >> 3) & 1) * 16);                // + ks*32

    // ---- prologue: prefetch first tile into registers ----
    float4 v[8];
    int t = blockIdx.x;
    {
        const float* bp = x + (size_t)t * 64 * 128;
#pragma unroll
        for (int it = 0; it < 8; ++it)
            v[it] = *(const float4*)&bp[(size_t)(st_row + 8 * it) * 128 + st_col];
    }

    int buf = 0;
    for (; t < NT2; t += gridDim.x, buf ^= 1) {
        const size_t m0 = (size_t)t * 64;
        const uint32_t abase = SM_A0 + (uint32_t)buf * 34816;

        // ---- convert + STS current tile (hi split, lo split) ----
#pragma unroll
        for (int it = 0; it < 8; ++it) {
            float h0 = __bfloat162float(__float2bfloat16(v[it].x));
            float h1 = __bfloat162float(__float2bfloat16(v[it].y));
            float h2 = __bfloat162float(__float2bfloat16(v[it].z));
            float h3 = __bfloat162float(__float2bfloat16(v[it].w));
            uint32_t off = (uint32_t)(st_row + 8 * it) * RSTRB + (uint32_t)st_col * 2;
            *(uint2*)(sm + abase + off) =
                make_uint2(bf16x2_of(h0, h1), bf16x2_of(h2, h3));
            *(uint2*)(sm + abase + 17408 + off) =
                make_uint2(bf16x2_of(v[it].x - h0, v[it].y - h1),
                           bf16x2_of(v[it].z - h2, v[it].w - h3));
        }
        __syncthreads();

        // ---- issue next tile's global loads (latency hides under MMA) ----
        int tn = t + gridDim.x;
        if (tn < NT2) {
            const float* bp = x + (size_t)tn * 64 * 128;
#pragma unroll
            for (int it = 0; it < 8; ++it)
                v[it] = *(const float4*)&bp[(size_t)(st_row + 8 * it) * 128 + st_col];
        }

        // ---- MMA: 3 split-pairs x 8 ksteps ----
        float c[2][8][4];
#pragma unroll
        for (int mf = 0; mf < 2; ++mf)
#pragma unroll
            for (int nf = 0; nf < 8; ++nf)
#pragma unroll
                for (int q = 0; q < 4; ++q) c[mf][nf][q] = 0.f;

#pragma unroll 1
        for (int split = 0; split < 3; ++split) {
            const uint32_t ab = smb + abase + ((split == 2) ? 17408u : 0u);
            const uint32_t bb = smb + ((split == 1) ? SM_BL : SM_BH);
#pragma unroll 1
            for (int ks = 0; ks < 8; ++ks) {
                const uint32_t kso = (uint32_t)ks * 32;
                uint32_t b[8][2];
#pragma unroll
                for (int nfp = 0; nfp < 4; ++nfp) {
                    uint32_t r0, r1, r2, r3;
                    ldsm4(r0, r1, r2, r3,
                          bb + (b_row + nfp * 16) * RSTRB + kso + b_kb);
                    b[2 * nfp][0] = r0; b[2 * nfp][1] = r1;
                    b[2 * nfp + 1][0] = r2; b[2 * nfp + 1][1] = r3;
                }
#pragma unroll
                for (int mf = 0; mf < 2; ++mf) {
                    uint32_t a0, a1, a2, a3;
                    ldsm4(a0, a1, a2, a3,
                          ab + (a_row + mf * 16) * RSTRB + kso + a_kb);
#pragma unroll
                    for (int nf = 0; nf < 8; ++nf)
                        mma16816(c[mf][nf], a0, a1, a2, a3, b[nf][0], b[nf][1]);
                }
            }
        }

        // ---- epilogue: scatter fragments to g_yz ----
#pragma unroll
        for (int mf = 0; mf < 2; ++mf) {
            size_t row = m0 + warp_m * 32 + mf * 16 + (lane >> 2);
#pragma unroll
            for (int nf = 0; nf < 8; ++nf) {
                int col = warp_n * 64 + nf * 8 + (lane & 3) * 2;
                *(float2*)&g_yz[row * 256 + col]       = make_float2(c[mf][nf][0], c[mf][nf][1]);
                *(float2*)&g_yz[(row + 8) * 256 + col] = make_float2(c[mf][nf][2], c[mf][nf][3]);
            }
        }
    }
}

// ---------------- gather + bias + LayerNorm + ReLU ----------------
__global__ void k_final(const float* __restrict__ bias,
                        const float* __restrict__ gamma,
                        const float* __restrict__ beta,
                        float* __restrict__ out) {
    const int row = blockIdx.x;
    const int i   = row & (NN - 1);
    const int b   = row >> 14;
    const int j   = threadIdx.x;

    float v = g_yz[(size_t)row * 256 + j];

    int st = g_rowstart[i];
    int en = g_rowstart[i + 1];
    float s = 0.f;
    for (int p = st; p < en; ++p) {
        int src = g_nbr[p] & (NN - 1);
        s += g_yz[((size_t)(b * NN + src)) * 256 + 128 + j];
    }
    float dg = (float)(en - st);
    v += s / fmaxf(dg, 1.f) + bias[j];

    __shared__ float red[4];
    const int lane = j & 31, wid = j >> 5;

    float t = v;
    t += __shfl_xor_sync(0xffffffff, t, 16);
    t += __shfl_xor_sync(0xffffffff, t, 8);
    t += __shfl_xor_sync(0xffffffff, t, 4);
    t += __shfl_xor_sync(0xffffffff, t, 2);
    t += __shfl_xor_sync(0xffffffff, t, 1);
    if (lane == 0) red[wid] = t;
    __syncthreads();
    float mu = (red[0] + red[1] + red[2] + red[3]) * (1.f / 128.f);
    __syncthreads();

    float c = v - mu;
    t = c * c;
    t += __shfl_xor_sync(0xffffffff, t, 16);
    t += __shfl_xor_sync(0xffffffff, t, 8);
    t += __shfl_xor_sync(0xffffffff, t, 4);
    t += __shfl_xor_sync(0xffffffff, t, 2);
    t += __shfl_xor_sync(0xffffffff, t, 1);
    if (lane == 0) red[wid] = t;
    __syncthreads();
    float var = (red[0] + red[1] + red[2] + red[3]) * (1.f / 128.f);

    float o = c * rsqrtf(var + 1e-5f) * gamma[j] + beta[j];
    out[(size_t)row * 128 + j] = fmaxf(o, 0.f);
}

// ---------------- launch ----------------
extern "C" void kernel_launch(void* const* d_in, const int* in_sizes, int n_in,
                              void* d_out, int out_size) {
    const float* x    = (const float*)d_in[0];
    const void*  edge = d_in[1];
    int base = n_in - 5;
    const float* Ws    = (const float*)d_in[base + 0];
    const float* Wn    = (const float*)d_in[base + 1];
    const float* bias  = (const float*)d_in[base + 2];
    const float* gamma = (const float*)d_in[base + 3];
    const float* beta  = (const float*)d_in[base + 4];

    cudaFuncSetAttribute(k_gemm_mma, cudaFuncAttributeMaxDynamicSharedMemorySize, SM_TOT);

    k_init<<<(NN + 255) / 256, 256>>>((const int*)edge);
    k_count<<<(EE + 255) / 256, 256>>>(edge);
    k_scan<<<1, 512>>>();
    k_fill<<<(EE + 255) / 256, 256>>>(edge);
    k_gemm_mma<<<152, 256, SM_TOT>>>(x, Ws, Wn);
    k_final<<<MM, 128>>>(bias, gamma, beta, (float*)d_out);
}